// round 5
// baseline (speedup 1.0000x reference)
#include <cuda_runtime.h>
#include <math_constants.h>

#define BB 64
#define JJ 32
#define MM 160
#define NN 160
#define HW (MM * NN)   // 25600
#define THREADS 256
#define NOBJ (BB * JJ) // 2048
#define VPT (HW / 4 / THREADS)   // 25 float4 loads per thread
#define NCHAIN 5

__device__ float g_perobj[NOBJ];
__device__ unsigned int g_count = 0;

// Fused: per-(b,j) argmax over 25600 floats + loss computation + last-block
// final batch reduction (no second kernel launch).
__global__ __launch_bounds__(THREADS) void argmax_loss_fused_kernel(
    const float* __restrict__ pred,
    const float* __restrict__ gt,
    const float* __restrict__ heatmap,
    float* __restrict__ out)
{
    const int bj = blockIdx.x;                 // 0 .. B*J-1
    const int tid = threadIdx.x;
    const float4* row = reinterpret_cast<const float4*>(heatmap + (size_t)bj * HW);

    // 5 independent comparator chains -> each chain consumes every 5th load,
    // so the FSETP/@p-select dependency never gates load issue.
    float cbest[NCHAIN];
    int   cidx[NCHAIN];
    #pragma unroll
    for (int c = 0; c < NCHAIN; c++) { cbest[c] = -CUDART_INF_F; cidx[c] = 0; }

    // Fully unrolled: 25 loads, deep front-batched LDG window (high MLP).
    #pragma unroll
    for (int m = 0; m < VPT; m++) {
        int i = tid + m * THREADS;
        float4 v = row[i];
        int base = i * 4;
        int c = m % NCHAIN;
        // strictly-greater keeps the earliest index within a chain
        // (i grows with m, so earlier iterations win ties)
        if (v.x > cbest[c]) { cbest[c] = v.x; cidx[c] = base; }
        if (v.y > cbest[c]) { cbest[c] = v.y; cidx[c] = base + 1; }
        if (v.z > cbest[c]) { cbest[c] = v.z; cidx[c] = base + 2; }
        if (v.w > cbest[c]) { cbest[c] = v.w; cidx[c] = base + 3; }
    }

    // Merge chains with global first-index tie-break.
    float best = cbest[0];
    int   bidx = cidx[0];
    #pragma unroll
    for (int c = 1; c < NCHAIN; c++) {
        if (cbest[c] > best || (cbest[c] == best && cidx[c] < bidx)) {
            best = cbest[c];
            bidx = cidx[c];
        }
    }

    __shared__ float svals[THREADS];
    __shared__ int   sidx[THREADS];
    __shared__ bool  is_last;
    svals[tid] = best;
    sidx[tid]  = bidx;
    __syncthreads();

    // tree reduction with first-index tie-break
    for (int s = THREADS / 2; s > 0; s >>= 1) {
        if (tid < s) {
            float ov = svals[tid + s];
            int   oi = sidx[tid + s];
            if (ov > svals[tid] || (ov == svals[tid] && oi < sidx[tid])) {
                svals[tid] = ov;
                sidx[tid]  = oi;
            }
        }
        __syncthreads();
    }

    if (tid == 0) {
        int idx = sidx[0];
        float x = (float)(idx / MM);   // reference: idx // m
        float y = (float)(idx % MM);   // reference: idx %  m

        int b = bj / JJ;
        int j = bj % JJ;

        const float* g = gt + ((size_t)b * JJ + j) * 11;
        float g7 = g[7], g8 = g[8], g9 = g[9], g10 = g[10];
        bool valid = (g9 > 0.0f) && (g10 > 0.0f) && (g9 < (float)MM) && (g10 < (float)NN);

        // pred layout: (B, 9, J, 1) -> pred[((b*9 + c)*J) + j]
        const float* pb = pred + (size_t)b * 9 * JJ + j;
        float px = pb[7 * JJ];
        float py = pb[8 * JJ];

        float dx = g9 + g7 - x - px;
        float dy = g10 + g8 - y - py;
        float loss = dx * dx + dy * dy;

        float cls = 0.0f;
        #pragma unroll
        for (int c = 0; c < 7; c++) {
            float d = pb[c * JJ] - g[c];
            cls = fmaf(d, d, cls);
        }

        g_perobj[bj] = valid ? (cls + loss) : 0.0f;

        // Publish, then count this block as done. The 2048th arrival elects
        // this block to do the final 2048 -> 64 reduction.
        __threadfence();
        unsigned int old = atomicAdd(&g_count, 1u);
        is_last = (old == NOBJ - 1);
    }
    __syncthreads();

    if (is_last) {
        // 64 threads each sum 32 per-joint losses for one batch.
        if (tid < BB) {
            float s = 0.0f;
            #pragma unroll
            for (int j = 0; j < JJ; j++)
                s += __ldcg(&g_perobj[tid * JJ + j]);  // L2 (fenced) read
            out[tid] = s;
        }
        if (tid == 0)
            g_count = 0;   // reset for next graph replay (deterministic)
    }
}

extern "C" void kernel_launch(void* const* d_in, const int* in_sizes, int n_in,
                              void* d_out, int out_size)
{
    const float* pred    = (const float*)d_in[0];
    const float* gt      = (const float*)d_in[1];
    const float* heatmap = (const float*)d_in[2];
    float* out = (float*)d_out;

    argmax_loss_fused_kernel<<<NOBJ, THREADS>>>(pred, gt, heatmap, out);
}

// round 6
// speedup vs baseline: 1.0674x; 1.0674x over previous
#include <cuda_runtime.h>
#include <math_constants.h>

#define BB 64
#define JJ 32
#define MM 160
#define NN 160
#define HW (MM * NN)   // 25600
#define THREADS 256
#define NWARP (THREADS / 32)
#define NOBJ (BB * JJ) // 2048

__device__ float g_perobj[NOBJ];
__device__ unsigned int g_count = 0;

// Fused: per-(b,j) argmax over 25600 floats + loss computation + last-block
// final batch reduction (no second kernel launch).
__global__ __launch_bounds__(THREADS) void argmax_loss_fused_kernel(
    const float* __restrict__ pred,
    const float* __restrict__ gt,
    const float* __restrict__ heatmap,
    float* __restrict__ out)
{
    const int bj = blockIdx.x;                 // 0 .. B*J-1
    const int tid = threadIdx.x;
    const float4* row = reinterpret_cast<const float4*>(heatmap + (size_t)bj * HW);

    float best = -CUDART_INF_F;
    int bidx = 0;

    // 6400 float4 per row; 256 threads -> 25 iterations each.
    // Moderate unroll: ~5 loads in flight per warp, serial comparator chain.
    // (Full 25-deep front-batching measured SLOWER: L1tex queue contention.)
    #pragma unroll 5
    for (int i = tid; i < HW / 4; i += THREADS) {
        float4 v = row[i];
        int base = i * 4;
        // strictly-greater keeps the earliest index within a thread
        if (v.x > best) { best = v.x; bidx = base; }
        if (v.y > best) { best = v.y; bidx = base + 1; }
        if (v.z > best) { best = v.z; bidx = base + 2; }
        if (v.w > best) { best = v.w; bidx = base + 3; }
    }

    // Warp-level reduction (no barriers): 5 shfl steps on (val, idx) pairs.
    #pragma unroll
    for (int off = 16; off > 0; off >>= 1) {
        float ov = __shfl_down_sync(0xFFFFFFFFu, best, off);
        int   oi = __shfl_down_sync(0xFFFFFFFFu, bidx, off);
        if (ov > best || (ov == best && oi < bidx)) { best = ov; bidx = oi; }
    }

    __shared__ float svals[NWARP];
    __shared__ int   sidx[NWARP];
    __shared__ bool  is_last;
    const int warp = tid >> 5;
    const int lane = tid & 31;
    if (lane == 0) { svals[warp] = best; sidx[warp] = bidx; }
    __syncthreads();

    if (tid == 0) {
        best = svals[0];
        bidx = sidx[0];
        #pragma unroll
        for (int w = 1; w < NWARP; w++) {
            float ov = svals[w];
            int   oi = sidx[w];
            if (ov > best || (ov == best && oi < bidx)) { best = ov; bidx = oi; }
        }

        int idx = bidx;
        float x = (float)(idx / MM);   // reference: idx // m
        float y = (float)(idx % MM);   // reference: idx %  m

        int b = bj / JJ;
        int j = bj % JJ;

        const float* g = gt + ((size_t)b * JJ + j) * 11;
        float g7 = g[7], g8 = g[8], g9 = g[9], g10 = g[10];
        bool valid = (g9 > 0.0f) && (g10 > 0.0f) && (g9 < (float)MM) && (g10 < (float)NN);

        // pred layout: (B, 9, J, 1) -> pred[((b*9 + c)*J) + j]
        const float* pb = pred + (size_t)b * 9 * JJ + j;
        float px = pb[7 * JJ];
        float py = pb[8 * JJ];

        float dx = g9 + g7 - x - px;
        float dy = g10 + g8 - y - py;
        float loss = dx * dx + dy * dy;

        float cls = 0.0f;
        #pragma unroll
        for (int c = 0; c < 7; c++) {
            float d = pb[c * JJ] - g[c];
            cls = fmaf(d, d, cls);
        }

        g_perobj[bj] = valid ? (cls + loss) : 0.0f;

        // Publish, then count this block as done. The 2048th arrival elects
        // this block to do the final 2048 -> 64 reduction.
        __threadfence();
        unsigned int old = atomicAdd(&g_count, 1u);
        is_last = (old == NOBJ - 1);
    }
    __syncthreads();

    if (is_last) {
        // 64 threads each sum 32 per-joint losses for one batch.
        if (tid < BB) {
            float s = 0.0f;
            #pragma unroll
            for (int j = 0; j < JJ; j++)
                s += __ldcg(&g_perobj[tid * JJ + j]);  // L2 (fenced) read
            out[tid] = s;
        }
        if (tid == 0)
            g_count = 0;   // reset for next graph replay (deterministic)
    }
}

extern "C" void kernel_launch(void* const* d_in, const int* in_sizes, int n_in,
                              void* d_out, int out_size)
{
    const float* pred    = (const float*)d_in[0];
    const float* gt      = (const float*)d_in[1];
    const float* heatmap = (const float*)d_in[2];
    float* out = (float*)d_out;

    argmax_loss_fused_kernel<<<NOBJ, THREADS>>>(pred, gt, heatmap, out);
}